// round 3
// baseline (speedup 1.0000x reference)
#include <cuda_runtime.h>
#include <math.h>

// Problem constants
#define BB   32
#define LSEQ 2048
#define DD   256
#define HH   64
#define YY   256
#define PCH  16   // l-chunks for pooling partials

// Scratch (device globals — no allocation allowed)
__device__ float g_z[(size_t)BB * LSEQ * HH];      // 16 MB: z = x@w1a + b1 (shared by both attention passes)
__device__ float g_slog[BB * LSEQ];
__device__ float g_elog[BB * LSEQ];
__device__ float g_yts[BB * HH];
__device__ float g_yte[BB * HH];
__device__ float g_pool_part[BB * PCH * DD];

// ---------------------------------------------------------------------------
// y_t for the s-pass: y_ts[b,h] = sum_d c0[b,d] * w2[a,d,h] + b2[a,h]
// ---------------------------------------------------------------------------
__global__ void k_yts(const float* __restrict__ c0, const int* __restrict__ actions,
                      const float* __restrict__ w2, const float* __restrict__ b2)
{
    int b = blockIdx.x, h = threadIdx.x;
    int a = actions[b];
    const float* w  = w2 + (size_t)a * DD * HH + h;
    const float* yb = c0 + b * DD;
    float acc = 0.f;
    #pragma unroll 4
    for (int d = 0; d < DD; d++) acc += yb[d] * w[d * HH];
    g_yts[b * HH + h] = acc + b2[a * HH + h];
}

// ---------------------------------------------------------------------------
// Main GEMM + s-score epilogue, software-pipelined.
// Per CTA: one batch b, 128 rows of L. Computes z[128][64] = x_tile @ w1a,
// stores z to scratch, and the s-logits (v . tanh(z + y_ts)) with mask.
// 256 threads, each owns a 4x8 register tile (rows rg+32i, cols c8+8j).
// Pipeline: LDG(kc+1) issued before FFMA(kc) so global latency overlaps math.
// ---------------------------------------------------------------------------
__global__ __launch_bounds__(256) void k_gemm_score(
    const float* __restrict__ x, const unsigned char* __restrict__ xmask,
    const int* __restrict__ actions,
    const float* __restrict__ w1, const float* __restrict__ b1,
    const float* __restrict__ v)
{
    __shared__ float Xs[32][129];   // k-major transposed x tile (pad 129: conflict-free)
    __shared__ float Wc[32][64];    // one 32-k chunk of w1a

    const int b  = blockIdx.y;
    const int l0 = blockIdx.x * 128;
    const int a  = actions[b];
    const float* wbase = w1 + (size_t)a * DD * HH;
    const float* xb    = x + ((size_t)b * LSEQ + l0) * DD;

    const int tid = threadIdx.x;
    const int c8 = tid & 7, rg = tid >> 3;      // compute mapping
    const int kk = tid & 7, l8 = tid >> 3;      // X load mapping
    const int hw = tid & 15, kw = tid >> 4;     // W load mapping

    float acc[4][8];
    #pragma unroll
    for (int i = 0; i < 4; i++)
        #pragma unroll
        for (int j = 0; j < 8; j++) acc[i][j] = 0.f;

    // Prefetch chunk 0 into registers
    float4 xv[4], wv[2];
    #pragma unroll
    for (int p = 0; p < 4; p++)
        xv[p] = *(const float4*)(xb + (size_t)(l8 + 32 * p) * DD + kk * 4);
    #pragma unroll
    for (int q = 0; q < 2; q++)
        wv[q] = *(const float4*)(wbase + (size_t)(kw + 16 * q) * HH + hw * 4);

    for (int kc = 0; kc < 8; kc++) {
        // Stage current chunk from registers into smem.
        // Xs[k][row] = x[b][l0+row][kc*32+k]; conflict-free (stride 129).
        #pragma unroll
        for (int p = 0; p < 4; p++) {
            int row = l8 + 32 * p;
            Xs[kk * 4 + 0][row] = xv[p].x;
            Xs[kk * 4 + 1][row] = xv[p].y;
            Xs[kk * 4 + 2][row] = xv[p].z;
            Xs[kk * 4 + 3][row] = xv[p].w;
        }
        #pragma unroll
        for (int q = 0; q < 2; q++) {
            int k = kw + 16 * q;
            Wc[k][hw * 4 + 0] = wv[q].x; Wc[k][hw * 4 + 1] = wv[q].y;
            Wc[k][hw * 4 + 2] = wv[q].z; Wc[k][hw * 4 + 3] = wv[q].w;
        }
        __syncthreads();

        // Prefetch next chunk (overlaps with the FFMA block below)
        if (kc < 7) {
            int koff = (kc + 1) * 32;
            #pragma unroll
            for (int p = 0; p < 4; p++)
                xv[p] = *(const float4*)(xb + (size_t)(l8 + 32 * p) * DD + koff + kk * 4);
            #pragma unroll
            for (int q = 0; q < 2; q++)
                wv[q] = *(const float4*)(wbase + (size_t)(koff + kw + 16 * q) * HH + hw * 4);
        }

        #pragma unroll 8
        for (int k = 0; k < 32; k++) {
            float aa[4], ww[8];
            #pragma unroll
            for (int i = 0; i < 4; i++) aa[i] = Xs[k][rg + 32 * i];
            #pragma unroll
            for (int j = 0; j < 8; j++) ww[j] = Wc[k][c8 + 8 * j];
            #pragma unroll
            for (int i = 0; i < 4; i++)
                #pragma unroll
                for (int j = 0; j < 8; j++)
                    acc[i][j] += aa[i] * ww[j];
        }
        __syncthreads();
    }

    // Epilogue: add b1, store z, compute s-scores
    float sp[4] = {0.f, 0.f, 0.f, 0.f};
    #pragma unroll
    for (int j = 0; j < 8; j++) {
        int h = c8 + 8 * j;
        float bb = b1[a * HH + h];
        float yt = g_yts[b * HH + h];
        float vv = v[a * HH + h];
        #pragma unroll
        for (int i = 0; i < 4; i++) {
            int row = rg + 32 * i;
            float z = acc[i][j] + bb;
            g_z[((size_t)b * LSEQ + l0 + row) * HH + h] = z;
            sp[i] += vv * tanhf(z + yt);
        }
    }
    // Reduce over c8 (lanes 0..7 of each 8-lane group share rg)
    #pragma unroll
    for (int i = 0; i < 4; i++) {
        float s = sp[i];
        s += __shfl_xor_sync(0xffffffffu, s, 1);
        s += __shfl_xor_sync(0xffffffffu, s, 2);
        s += __shfl_xor_sync(0xffffffffu, s, 4);
        if (c8 == 0) {
            int l = l0 + rg + 32 * i;
            g_slog[b * LSEQ + l] = xmask[b * LSEQ + l] ? -1e30f : s;
        }
    }
}

// ---------------------------------------------------------------------------
// Row softmax over L=2048. which=0 -> g_slog, which=1 -> g_elog
// ---------------------------------------------------------------------------
__global__ __launch_bounds__(256) void k_softmax(int which, float* __restrict__ probs)
{
    __shared__ float red[256];
    int b = blockIdx.x, tid = threadIdx.x;
    const float* in = (which == 0 ? g_slog : g_elog) + b * LSEQ;
    float vals[8];
    float m = -INFINITY;
    #pragma unroll
    for (int i = 0; i < 8; i++) { vals[i] = in[tid + 256 * i]; m = fmaxf(m, vals[i]); }
    red[tid] = m; __syncthreads();
    for (int s = 128; s > 0; s >>= 1) { if (tid < s) red[tid] = fmaxf(red[tid], red[tid + s]); __syncthreads(); }
    m = red[0]; __syncthreads();
    float sum = 0.f;
    #pragma unroll
    for (int i = 0; i < 8; i++) { vals[i] = expf(vals[i] - m); sum += vals[i]; }
    red[tid] = sum; __syncthreads();
    for (int s = 128; s > 0; s >>= 1) { if (tid < s) red[tid] += red[tid + s]; __syncthreads(); }
    float inv = 1.f / red[0];
    float* outp = probs + b * LSEQ;
    #pragma unroll
    for (int i = 0; i < 8; i++) outp[tid + 256 * i] = vals[i] * inv;
}

// ---------------------------------------------------------------------------
// attn_pool partials: pool_part[b,c,d] = sum over l-chunk of x[b,l,d]*p[b,l]
// ---------------------------------------------------------------------------
__global__ __launch_bounds__(256) void k_pool(const float* __restrict__ x,
                                              const float* __restrict__ probs)
{
    __shared__ float ps[128];
    int c = blockIdx.x, b = blockIdx.y, tid = threadIdx.x;
    if (tid < 128) ps[tid] = probs[b * LSEQ + c * 128 + tid];
    __syncthreads();
    const float* xp = x + ((size_t)b * LSEQ + c * 128) * DD + tid;
    float acc = 0.f;
    #pragma unroll 4
    for (int l = 0; l < 128; l++) acc += xp[(size_t)l * DD] * ps[l];
    g_pool_part[(b * PCH + c) * DD + tid] = acc;
}

// ---------------------------------------------------------------------------
// SRU cell + y_t for the e-pass.
// ---------------------------------------------------------------------------
__global__ __launch_bounds__(256) void k_sru(const float* __restrict__ c0,
    const float* __restrict__ w_sru, const float* __restrict__ b_sru,
    const int* __restrict__ actions,
    const float* __restrict__ w2, const float* __restrict__ b2)
{
    __shared__ float pool[DD];
    __shared__ float state[YY];
    int b = blockIdx.x, tid = threadIdx.x;
    float acc = 0.f;
    #pragma unroll
    for (int c = 0; c < PCH; c++) acc += g_pool_part[(b * PCH + c) * DD + tid];
    pool[tid] = acc;
    __syncthreads();

    // u[:, tid] (x_tilde) and u[:, 256+tid] (f-gate pre-activation)
    float u0 = 0.f, u1 = 0.f;
    #pragma unroll 4
    for (int d = 0; d < DD; d++) {
        float pv = pool[d];
        u0 += pv * w_sru[d * 768 + tid];
        u1 += pv * w_sru[d * 768 + 256 + tid];
    }
    float f = 1.f / (1.f + expf(-(u1 + b_sru[tid])));
    state[tid] = f * c0[b * DD + tid] + (1.f - f) * u0;
    __syncthreads();

    if (tid < HH) {
        int a = actions[b];
        const float* w = w2 + (size_t)a * DD * HH + tid;
        float yt = 0.f;
        #pragma unroll 4
        for (int d = 0; d < DD; d++) yt += state[d] * w[d * HH];
        g_yte[b * HH + tid] = yt + b2[a * HH + tid];
    }
}

// ---------------------------------------------------------------------------
// e-scores from cached z: e_logit[b,l] = sum_h v[h]*tanh(z[b,l,h] + y_te[b,h])
// one warp per l-row, 2 rows per warp iteration (16 rows per CTA).
// ---------------------------------------------------------------------------
__global__ __launch_bounds__(256) void k_escore(const unsigned char* __restrict__ xmask,
    const int* __restrict__ actions, const float* __restrict__ v)
{
    int b = blockIdx.y;
    int wid = threadIdx.x >> 5, lane = threadIdx.x & 31;
    int a = actions[b];
    float y0 = g_yte[b * HH + lane], y1 = g_yte[b * HH + lane + 32];
    float v0 = v[a * HH + lane],     v1 = v[a * HH + lane + 32];
    #pragma unroll
    for (int r = 0; r < 2; r++) {
        int l = blockIdx.x * 16 + wid * 2 + r;
        const float* zp = g_z + ((size_t)b * LSEQ + l) * HH;
        float t0 = zp[lane], t1 = zp[lane + 32];
        float s = v0 * tanhf(t0 + y0) + v1 * tanhf(t1 + y1);
        #pragma unroll
        for (int o = 16; o > 0; o >>= 1) s += __shfl_xor_sync(0xffffffffu, s, o);
        if (lane == 0) g_elog[b * LSEQ + l] = xmask[b * LSEQ + l] ? -1e30f : s;
    }
}

// ---------------------------------------------------------------------------
extern "C" void kernel_launch(void* const* d_in, const int* in_sizes, int n_in,
                              void* d_out, int out_size)
{
    const float*         x      = (const float*)d_in[0];
    const unsigned char* xmask  = (const unsigned char*)d_in[1];
    const float*         c0     = (const float*)d_in[2];
    const int*           actions= (const int*)d_in[3];
    const float*         w1     = (const float*)d_in[4];
    const float*         b1     = (const float*)d_in[5];
    const float*         w2     = (const float*)d_in[6];
    const float*         b2     = (const float*)d_in[7];
    const float*         v      = (const float*)d_in[8];
    const float*         w_sru  = (const float*)d_in[9];
    const float*         b_sru  = (const float*)d_in[10];
    float* out = (float*)d_out;   // [0:65536) = s_probs, [65536:131072) = e_probs

    k_yts<<<BB, HH>>>(c0, actions, w2, b2);
    k_gemm_score<<<dim3(LSEQ / 128, BB), 256>>>(x, xmask, actions, w1, b1, v);
    k_softmax<<<BB, 256>>>(0, out);                        // s_probs
    k_pool<<<dim3(PCH, BB), 256>>>(x, out);
    k_sru<<<BB, 256>>>(c0, w_sru, b_sru, actions, w2, b2);
    k_escore<<<dim3(LSEQ / 16, BB), 256>>>(xmask, actions, v);
    k_softmax<<<BB, 256>>>(1, out + BB * LSEQ);            // e_probs
}

// round 4
// speedup vs baseline: 1.1584x; 1.1584x over previous
#include <cuda_runtime.h>
#include <math.h>

// Problem constants
#define BB   32
#define LSEQ 2048
#define DD   256
#define HH   64
#define YY   256
#define NP   64   // pooling partials per batch (16 l-chunks x 4 row-groups)

// Scratch (device globals — no allocation allowed)
__device__ float g_z[(size_t)BB * LSEQ * HH];      // 16 MB: z = x@w1a + b1 (shared by both passes)
__device__ float g_slog[BB * LSEQ];
__device__ float g_elog[BB * LSEQ];
__device__ float g_yts[BB * HH];
__device__ float g_yte[BB * HH];
__device__ float g_pool_part[BB * NP * DD];

// ---------------------------------------------------------------------------
// y_t (s-pass): y_ts[b,h] = sum_d c0[b,d]*w2[a,d,h] + b2[a,h]
// 256 threads: h = tid&63 (coalesced over w2's h dim), q = tid>>6 splits d 4-way.
// ---------------------------------------------------------------------------
__global__ __launch_bounds__(256) void k_yts(const float* __restrict__ c0,
    const int* __restrict__ actions,
    const float* __restrict__ w2, const float* __restrict__ b2)
{
    __shared__ float red[4][64];
    int b = blockIdx.x, tid = threadIdx.x;
    int h = tid & 63, q = tid >> 6;
    int a = actions[b];
    const float* w  = w2 + (size_t)a * DD * HH + h;
    const float* yb = c0 + b * DD;
    float acc = 0.f;
    #pragma unroll 8
    for (int d = q * 64; d < q * 64 + 64; d++) acc += yb[d] * w[(size_t)d * HH];
    red[q][h] = acc;
    __syncthreads();
    if (q == 0)
        g_yts[b * HH + h] = red[0][h] + red[1][h] + red[2][h] + red[3][h] + b2[a * HH + h];
}

// ---------------------------------------------------------------------------
// Main GEMM + s-score epilogue, software-pipelined.
// Per CTA: one batch b, 128 rows of L. z[128][64] = x_tile @ w1a (+b1) cached
// to g_z, plus s-logits. 256 threads; each owns rows rg+32i (i<4) and the
// CONTIGUOUS column octet c8*8..c8*8+7 -> Wc reads are 2x LDS.128 per k.
// ---------------------------------------------------------------------------
__global__ __launch_bounds__(256) void k_gemm_score(
    const float* __restrict__ x, const unsigned char* __restrict__ xmask,
    const int* __restrict__ actions,
    const float* __restrict__ w1, const float* __restrict__ b1,
    const float* __restrict__ v)
{
    __shared__ float Xs[32][129];   // k-major transposed x tile (pad: conflict-free STS/LDS)
    __shared__ float Wc[32][64];    // one 32-k chunk of w1a

    const int b  = blockIdx.y;
    const int l0 = blockIdx.x * 128;
    const int a  = actions[b];
    const float* wbase = w1 + (size_t)a * DD * HH;
    const float* xb    = x + ((size_t)b * LSEQ + l0) * DD;

    const int tid = threadIdx.x;
    const int c8 = tid & 7, rg = tid >> 3;      // compute mapping (cols c8*8.., rows rg+32i)
    const int kk = tid & 7, l8 = tid >> 3;      // X load mapping
    const int hw = tid & 15, kw = tid >> 4;     // W load mapping

    float acc[4][8];
    #pragma unroll
    for (int i = 0; i < 4; i++)
        #pragma unroll
        for (int j = 0; j < 8; j++) acc[i][j] = 0.f;

    // Prefetch chunk 0 into registers
    float4 xv[4], wv[2];
    #pragma unroll
    for (int p = 0; p < 4; p++)
        xv[p] = *(const float4*)(xb + (size_t)(l8 + 32 * p) * DD + kk * 4);
    #pragma unroll
    for (int q = 0; q < 2; q++)
        wv[q] = *(const float4*)(wbase + (size_t)(kw + 16 * q) * HH + hw * 4);

    for (int kc = 0; kc < 8; kc++) {
        // Stage current chunk (regs -> smem)
        #pragma unroll
        for (int p = 0; p < 4; p++) {
            int row = l8 + 32 * p;
            Xs[kk * 4 + 0][row] = xv[p].x;
            Xs[kk * 4 + 1][row] = xv[p].y;
            Xs[kk * 4 + 2][row] = xv[p].z;
            Xs[kk * 4 + 3][row] = xv[p].w;
        }
        #pragma unroll
        for (int q = 0; q < 2; q++) {
            int k = kw + 16 * q;
            *(float4*)&Wc[k][hw * 4] = wv[q];
        }
        __syncthreads();

        // Prefetch next chunk (overlaps the FFMA block)
        if (kc < 7) {
            int koff = (kc + 1) * 32;
            #pragma unroll
            for (int p = 0; p < 4; p++)
                xv[p] = *(const float4*)(xb + (size_t)(l8 + 32 * p) * DD + koff + kk * 4);
            #pragma unroll
            for (int q = 0; q < 2; q++)
                wv[q] = *(const float4*)(wbase + (size_t)(koff + kw + 16 * q) * HH + hw * 4);
        }

        #pragma unroll 8
        for (int k = 0; k < 32; k++) {
            float aa[4];
            #pragma unroll
            for (int i = 0; i < 4; i++) aa[i] = Xs[k][rg + 32 * i];
            float4 w0 = *(const float4*)&Wc[k][c8 * 8];
            float4 w1v = *(const float4*)&Wc[k][c8 * 8 + 4];
            #pragma unroll
            for (int i = 0; i < 4; i++) {
                acc[i][0] += aa[i] * w0.x;  acc[i][1] += aa[i] * w0.y;
                acc[i][2] += aa[i] * w0.z;  acc[i][3] += aa[i] * w0.w;
                acc[i][4] += aa[i] * w1v.x; acc[i][5] += aa[i] * w1v.y;
                acc[i][6] += aa[i] * w1v.z; acc[i][7] += aa[i] * w1v.w;
            }
        }
        __syncthreads();
    }

    // Epilogue: add b1, store z (vectorized), compute s-scores
    const int hb = c8 * 8;
    float4 bb0 = *(const float4*)(b1 + a * HH + hb);
    float4 bb1 = *(const float4*)(b1 + a * HH + hb + 4);
    float4 yt0 = *(const float4*)(&g_yts[b * HH + hb]);
    float4 yt1 = *(const float4*)(&g_yts[b * HH + hb + 4]);
    float4 vv0 = *(const float4*)(v + a * HH + hb);
    float4 vv1 = *(const float4*)(v + a * HH + hb + 4);

    float sp[4];
    #pragma unroll
    for (int i = 0; i < 4; i++) {
        int row = rg + 32 * i;
        float4 z0, z1;
        z0.x = acc[i][0] + bb0.x; z0.y = acc[i][1] + bb0.y;
        z0.z = acc[i][2] + bb0.z; z0.w = acc[i][3] + bb0.w;
        z1.x = acc[i][4] + bb1.x; z1.y = acc[i][5] + bb1.y;
        z1.z = acc[i][6] + bb1.z; z1.w = acc[i][7] + bb1.w;
        float* zr = g_z + ((size_t)b * LSEQ + l0 + row) * HH + hb;
        *(float4*)zr = z0;
        *(float4*)(zr + 4) = z1;
        float s;
        s  = vv0.x * tanhf(z0.x + yt0.x);
        s += vv0.y * tanhf(z0.y + yt0.y);
        s += vv0.z * tanhf(z0.z + yt0.z);
        s += vv0.w * tanhf(z0.w + yt0.w);
        s += vv1.x * tanhf(z1.x + yt1.x);
        s += vv1.y * tanhf(z1.y + yt1.y);
        s += vv1.z * tanhf(z1.z + yt1.z);
        s += vv1.w * tanhf(z1.w + yt1.w);
        sp[i] = s;
    }
    #pragma unroll
    for (int i = 0; i < 4; i++) {
        float s = sp[i];
        s += __shfl_xor_sync(0xffffffffu, s, 1);
        s += __shfl_xor_sync(0xffffffffu, s, 2);
        s += __shfl_xor_sync(0xffffffffu, s, 4);
        if (c8 == 0) {
            int l = l0 + rg + 32 * i;
            g_slog[b * LSEQ + l] = xmask[b * LSEQ + l] ? -1e30f : s;
        }
    }
}

// ---------------------------------------------------------------------------
// Row softmax over L=2048. which=0 -> g_slog, which=1 -> g_elog
// ---------------------------------------------------------------------------
__global__ __launch_bounds__(256) void k_softmax(int which, float* __restrict__ probs)
{
    __shared__ float red[256];
    int b = blockIdx.x, tid = threadIdx.x;
    const float* in = (which == 0 ? g_slog : g_elog) + b * LSEQ;
    float vals[8];
    float m = -INFINITY;
    #pragma unroll
    for (int i = 0; i < 8; i++) { vals[i] = in[tid + 256 * i]; m = fmaxf(m, vals[i]); }
    red[tid] = m; __syncthreads();
    for (int s = 128; s > 0; s >>= 1) { if (tid < s) red[tid] = fmaxf(red[tid], red[tid + s]); __syncthreads(); }
    m = red[0]; __syncthreads();
    float sum = 0.f;
    #pragma unroll
    for (int i = 0; i < 8; i++) { vals[i] = expf(vals[i] - m); sum += vals[i]; }
    red[tid] = sum; __syncthreads();
    for (int s = 128; s > 0; s >>= 1) { if (tid < s) red[tid] += red[tid + s]; __syncthreads(); }
    float inv = 1.f / red[0];
    float* outp = probs + b * LSEQ;
    #pragma unroll
    for (int i = 0; i < 8; i++) outp[tid + 256 * i] = vals[i] * inv;
}

// ---------------------------------------------------------------------------
// attn_pool partials: high-MLP vectorized version.
// grid (16, B), 256 threads: d4 = tid&63 owns a float4 of D; lg = tid>>6 owns
// 32 of the CTA's 128 l-rows. 32 independent LDG.128 per thread.
// partial p = c*4+lg  (NP=64 per batch), summed by k_sru.
// ---------------------------------------------------------------------------
__global__ __launch_bounds__(256) void k_pool(const float* __restrict__ x,
                                              const float* __restrict__ probs)
{
    __shared__ float ps[128];
    int c = blockIdx.x, b = blockIdx.y, tid = threadIdx.x;
    int d4 = tid & 63, lg = tid >> 6;
    if (tid < 128) ps[tid] = probs[b * LSEQ + c * 128 + tid];
    __syncthreads();
    const float* xp = x + ((size_t)b * LSEQ + c * 128 + lg * 32) * DD + d4 * 4;
    const float* pp = ps + lg * 32;
    float4 acc = make_float4(0.f, 0.f, 0.f, 0.f);
    #pragma unroll 8
    for (int l = 0; l < 32; l++) {
        float4 xv = *(const float4*)(xp + (size_t)l * DD);
        float p = pp[l];
        acc.x += xv.x * p; acc.y += xv.y * p;
        acc.z += xv.z * p; acc.w += xv.w * p;
    }
    *(float4*)(&g_pool_part[((size_t)(b * 16 + c) * 4 + lg) * DD + d4 * 4]) = acc;
}

// ---------------------------------------------------------------------------
// SRU cell + y_t for the e-pass.
// ---------------------------------------------------------------------------
__global__ __launch_bounds__(256) void k_sru(const float* __restrict__ c0,
    const float* __restrict__ w_sru, const float* __restrict__ b_sru,
    const int* __restrict__ actions,
    const float* __restrict__ w2, const float* __restrict__ b2)
{
    __shared__ float pool[DD];
    __shared__ float state[YY];
    int b = blockIdx.x, tid = threadIdx.x;
    float acc0 = 0.f, acc1 = 0.f;
    #pragma unroll
    for (int c = 0; c < NP; c += 2) {
        acc0 += g_pool_part[((size_t)b * NP + c) * DD + tid];
        acc1 += g_pool_part[((size_t)b * NP + c + 1) * DD + tid];
    }
    pool[tid] = acc0 + acc1;
    __syncthreads();

    // u[:, tid] (x_tilde) and u[:, 256+tid] (f-gate pre-activation)
    float u0 = 0.f, u1 = 0.f;
    #pragma unroll 8
    for (int d = 0; d < DD; d++) {
        float pv = pool[d];
        u0 += pv * w_sru[d * 768 + tid];
        u1 += pv * w_sru[d * 768 + 256 + tid];
    }
    float f = 1.f / (1.f + expf(-(u1 + b_sru[tid])));
    state[tid] = f * c0[b * DD + tid] + (1.f - f) * u0;
    __syncthreads();

    // y_te[b,h]: 4-way d-split like k_yts
    int h = tid & 63, q = tid >> 6;
    int a = actions[b];
    const float* w = w2 + (size_t)a * DD * HH + h;
    float yt = 0.f;
    #pragma unroll 8
    for (int d = q * 64; d < q * 64 + 64; d++) yt += state[d] * w[(size_t)d * HH];
    __syncthreads();
    pool[tid] = yt;   // reuse smem as [4][64]
    __syncthreads();
    if (q == 0)
        g_yte[b * HH + h] = pool[h] + pool[64 + h] + pool[128 + h] + pool[192 + h]
                            + b2[a * HH + h];
}

// ---------------------------------------------------------------------------
// e-scores from cached z. float2 per lane, 4 rows per warp (32 rows per CTA).
// ---------------------------------------------------------------------------
__global__ __launch_bounds__(256) void k_escore(const unsigned char* __restrict__ xmask,
    const int* __restrict__ actions, const float* __restrict__ v)
{
    int b = blockIdx.y;
    int wid = threadIdx.x >> 5, lane = threadIdx.x & 31;
    int a = actions[b];
    float2 yv = *(const float2*)(&g_yte[b * HH + 2 * lane]);
    float2 vv = *(const float2*)(v + a * HH + 2 * lane);
    #pragma unroll
    for (int r = 0; r < 4; r++) {
        int l = blockIdx.x * 32 + wid * 4 + r;
        float2 z2 = *(const float2*)(&g_z[((size_t)b * LSEQ + l) * HH + 2 * lane]);
        float s = vv.x * tanhf(z2.x + yv.x) + vv.y * tanhf(z2.y + yv.y);
        #pragma unroll
        for (int o = 16; o > 0; o >>= 1) s += __shfl_xor_sync(0xffffffffu, s, o);
        if (lane == 0) g_elog[b * LSEQ + l] = xmask[b * LSEQ + l] ? -1e30f : s;
    }
}

// ---------------------------------------------------------------------------
extern "C" void kernel_launch(void* const* d_in, const int* in_sizes, int n_in,
                              void* d_out, int out_size)
{
    const float*         x      = (const float*)d_in[0];
    const unsigned char* xmask  = (const unsigned char*)d_in[1];
    const float*         c0     = (const float*)d_in[2];
    const int*           actions= (const int*)d_in[3];
    const float*         w1     = (const float*)d_in[4];
    const float*         b1     = (const float*)d_in[5];
    const float*         w2     = (const float*)d_in[6];
    const float*         b2     = (const float*)d_in[7];
    const float*         v      = (const float*)d_in[8];
    const float*         w_sru  = (const float*)d_in[9];
    const float*         b_sru  = (const float*)d_in[10];
    float* out = (float*)d_out;   // [0:65536) = s_probs, [65536:131072) = e_probs

    k_yts<<<BB, 256>>>(c0, actions, w2, b2);
    k_gemm_score<<<dim3(LSEQ / 128, BB), 256>>>(x, xmask, actions, w1, b1, v);
    k_softmax<<<BB, 256>>>(0, out);                        // s_probs
    k_pool<<<dim3(16, BB), 256>>>(x, out);
    k_sru<<<BB, 256>>>(c0, w_sru, b_sru, actions, w2, b2);
    k_escore<<<dim3(LSEQ / 32, BB), 256>>>(xmask, actions, v);
    k_softmax<<<BB, 256>>>(1, out + BB * LSEQ);            // e_probs
}